// round 1
// baseline (speedup 1.0000x reference)
#include <cuda_runtime.h>
#include <math.h>

// lpLSTM: T=512 steps, B=64 batch, IN=1024, H=1024.
// Inputs (metadata order):
//  0: input_ [512,64,1024]  1: h0 [1,64,1024]  2: c0 [1,64,1024]
//  3..6:  w_xi w_xf w_xo w_xc  [1024,1024] (row-major [k][h])
//  7..10: w_hi w_hf w_ho w_hc  [1024,1024] (row-major [k][h])
//  11..14: b_i b_f b_o b_c [1024]
//  15: retention_ratio [1024]
// Output: outs [512,64,1024] ++ h_T [1,64,1024] ++ c_T [1,64,1024] (float32)

#define T_STEPS 512
#define BATCH   64
#define INDIM   1024
#define HDIM    1024

// Gate preactivation scratch: [gate][t][b][h] planes. 4 * 512*64*1024 fp32 = 512 MB.
__device__ float g_G[4ULL * T_STEPS * BATCH * HDIM];
// Cell state [b][h]
__device__ float g_c[BATCH * HDIM];

// ---------------------------------------------------------------------------
// Kernel 1: x-projection GEMM.  G[g][m][n] = X[m,:] @ Wx_g[:,n] + b_g[n]
// M = T*B = 32768, N = 1024, K = 1024, grid.z = gate.
// Tile 64x64, BK=16, 256 threads, 4x4 microtile.
// ---------------------------------------------------------------------------
__global__ __launch_bounds__(256) void xproj_kernel(
    const float* __restrict__ X,
    const float* __restrict__ Wi, const float* __restrict__ Wf,
    const float* __restrict__ Wo, const float* __restrict__ Wc,
    const float* __restrict__ bi, const float* __restrict__ bf,
    const float* __restrict__ bo, const float* __restrict__ bc)
{
    const int g = blockIdx.z;
    const float* W    = (g == 0) ? Wi : (g == 1) ? Wf : (g == 2) ? Wo : Wc;
    const float* bias = (g == 0) ? bi : (g == 1) ? bf : (g == 2) ? bo : bc;
    float* Cout = g_G + (size_t)g * T_STEPS * BATCH * HDIM;

    const int m0 = blockIdx.y * 64;
    const int n0 = blockIdx.x * 64;
    const int tid = threadIdx.x;
    const int tn = tid & 15;   // 0..15 -> 4 output cols
    const int tm = tid >> 4;   // 0..15 -> 4 output rows

    __shared__ float As[16][65];   // [k][m], padded
    __shared__ float Bs[16][64];   // [k][n]

    float acc[4][4];
#pragma unroll
    for (int i = 0; i < 4; i++)
#pragma unroll
        for (int j = 0; j < 4; j++) acc[i][j] = 0.0f;

    const int ar  = tid >> 2;        // 0..63 : A row within tile
    const int ak  = (tid & 3) * 4;   // 0,4,8,12 : A k offset
    const int brr = tid >> 4;        // 0..15 : B k row
    const int bc4 = (tid & 15) * 4;  // B col offset

    for (int k0 = 0; k0 < INDIM; k0 += 16) {
        float4 av = *(const float4*)(X + (size_t)(m0 + ar) * INDIM + k0 + ak);
        float4 bv = *(const float4*)(W + (size_t)(k0 + brr) * HDIM + n0 + bc4);
        As[ak + 0][ar] = av.x;
        As[ak + 1][ar] = av.y;
        As[ak + 2][ar] = av.z;
        As[ak + 3][ar] = av.w;
        *(float4*)&Bs[brr][bc4] = bv;
        __syncthreads();

#pragma unroll
        for (int k = 0; k < 16; k++) {
            float a0 = As[k][tm * 4 + 0];
            float a1 = As[k][tm * 4 + 1];
            float a2 = As[k][tm * 4 + 2];
            float a3 = As[k][tm * 4 + 3];
            float4 bb = *(float4*)&Bs[k][tn * 4];
            acc[0][0] += a0 * bb.x; acc[0][1] += a0 * bb.y; acc[0][2] += a0 * bb.z; acc[0][3] += a0 * bb.w;
            acc[1][0] += a1 * bb.x; acc[1][1] += a1 * bb.y; acc[1][2] += a1 * bb.z; acc[1][3] += a1 * bb.w;
            acc[2][0] += a2 * bb.x; acc[2][1] += a2 * bb.y; acc[2][2] += a2 * bb.z; acc[2][3] += a2 * bb.w;
            acc[3][0] += a3 * bb.x; acc[3][1] += a3 * bb.y; acc[3][2] += a3 * bb.z; acc[3][3] += a3 * bb.w;
        }
        __syncthreads();
    }

    const float b0 = bias[n0 + tn * 4 + 0];
    const float b1 = bias[n0 + tn * 4 + 1];
    const float b2 = bias[n0 + tn * 4 + 2];
    const float b3 = bias[n0 + tn * 4 + 3];
#pragma unroll
    for (int i = 0; i < 4; i++) {
        float4 v;
        v.x = acc[i][0] + b0;
        v.y = acc[i][1] + b1;
        v.z = acc[i][2] + b2;
        v.w = acc[i][3] + b3;
        *(float4*)(Cout + (size_t)(m0 + tm * 4 + i) * HDIM + n0 + tn * 4) = v;
    }
}

// ---------------------------------------------------------------------------
// Kernel 2: one recurrence step (fused 4-gate hidden GEMM + LSTM elementwise).
// Grid: 128 CTAs, each owns 8 h-columns for all 64 batch rows and all 4 gates.
// 256 threads: tid -> (b0 = tid&31, hl = tid>>5); each thread computes
// batch rows {b0, b0+32} for one h column, 4 gates = 8 accumulators.
// ---------------------------------------------------------------------------
__global__ __launch_bounds__(256) void step_kernel(
    const float* __restrict__ Whi, const float* __restrict__ Whf,
    const float* __restrict__ Who, const float* __restrict__ Whc,
    const float* __restrict__ ret,
    const float* __restrict__ h_prev,  // [B][H]
    float* __restrict__ h_out,         // [B][H] (= outs[t])
    int t)
{
    __shared__ float sh_h[BATCH][33];     // [b][k], padded
    __shared__ float sh_w[4][32][8];      // [gate][k][h_local]

    const int tid = threadIdx.x;
    const int b0  = tid & 31;
    const int hl  = tid >> 5;                 // 0..7
    const int hbase = blockIdx.x * 8;
    const int hcol  = hbase + hl;

    float acc[2][4];
#pragma unroll
    for (int i = 0; i < 2; i++)
#pragma unroll
        for (int j = 0; j < 4; j++) acc[i][j] = 0.0f;

    // weight load mapping: 256 threads load 4 gates x 32 k x 8 h = 1024 floats
    const int wg = tid >> 6;            // gate 0..3
    const int wk = (tid & 63) >> 1;     // k row 0..31
    const int wp = (tid & 1) * 4;       // 0 or 4
    const float* Wsel = (wg == 0) ? Whi : (wg == 1) ? Whf : (wg == 2) ? Who : Whc;

    for (int k0 = 0; k0 < HDIM; k0 += 32) {
        // load h tile: 64 rows x 32 k = 512 float4, 2 per thread
#pragma unroll
        for (int j = 0; j < 2; j++) {
            int idx = tid * 2 + j;
            int row = idx >> 3;
            int c4  = (idx & 7) * 4;
            float4 v = *(const float4*)(h_prev + (size_t)row * HDIM + k0 + c4);
            sh_h[row][c4 + 0] = v.x;
            sh_h[row][c4 + 1] = v.y;
            sh_h[row][c4 + 2] = v.z;
            sh_h[row][c4 + 3] = v.w;
        }
        {
            float4 wv = *(const float4*)(Wsel + (size_t)(k0 + wk) * HDIM + hbase + wp);
            *(float4*)&sh_w[wg][wk][wp] = wv;
        }
        __syncthreads();

#pragma unroll
        for (int k = 0; k < 32; k++) {
            float a0 = sh_h[b0][k];
            float a1 = sh_h[b0 + 32][k];
            float w0 = sh_w[0][k][hl];
            float w1 = sh_w[1][k][hl];
            float w2 = sh_w[2][k][hl];
            float w3 = sh_w[3][k][hl];
            acc[0][0] += a0 * w0; acc[0][1] += a0 * w1;
            acc[0][2] += a0 * w2; acc[0][3] += a0 * w3;
            acc[1][0] += a1 * w0; acc[1][1] += a1 * w1;
            acc[1][2] += a1 * w2; acc[1][3] += a1 * w3;
        }
        __syncthreads();
    }

    const size_t plane = (size_t)T_STEPS * BATCH * HDIM;
    const size_t tb    = (size_t)t * BATCH * HDIM;
    const float  r     = ret[hcol];

#pragma unroll
    for (int bi = 0; bi < 2; bi++) {
        const int    b   = b0 + bi * 32;
        const size_t idx = (size_t)b * HDIM + hcol;
        float gi = g_G[0 * plane + tb + idx] + acc[bi][0];
        float gf = g_G[1 * plane + tb + idx] + acc[bi][1];
        float go = g_G[2 * plane + tb + idx] + acc[bi][2];
        float gc = g_G[3 * plane + tb + idx] + acc[bi][3];

        float i_t = 1.0f / (1.0f + expf(-gi));
        float f_t = 1.0f / (1.0f + expf(-gf));
        float o_t = 1.0f / (1.0f + expf(-go));
        float g_t = tanhf(gc);

        float c_old = g_c[idx];
        float c_new = c_old * f_t + i_t * g_t;
        g_c[idx] = c_new;

        float h_lstm = o_t * tanhf(c_new);
        float hp     = h_prev[idx];
        h_out[idx]   = r * hp + (1.0f - r) * h_lstm;
    }
}

// ---------------------------------------------------------------------------
extern "C" void kernel_launch(void* const* d_in, const int* in_sizes, int n_in,
                              void* d_out, int out_size)
{
    const float* X    = (const float*)d_in[0];
    const float* h0   = (const float*)d_in[1];
    const float* c0   = (const float*)d_in[2];
    const float* w_xi = (const float*)d_in[3];
    const float* w_xf = (const float*)d_in[4];
    const float* w_xo = (const float*)d_in[5];
    const float* w_xc = (const float*)d_in[6];
    const float* w_hi = (const float*)d_in[7];
    const float* w_hf = (const float*)d_in[8];
    const float* w_ho = (const float*)d_in[9];
    const float* w_hc = (const float*)d_in[10];
    const float* b_i  = (const float*)d_in[11];
    const float* b_f  = (const float*)d_in[12];
    const float* b_o  = (const float*)d_in[13];
    const float* b_c  = (const float*)d_in[14];
    const float* rr   = (const float*)d_in[15];

    float* out = (float*)d_out;

    // cell-state scratch address (query, not an allocation)
    void* c_ptr = nullptr;
    cudaGetSymbolAddress(&c_ptr, g_c);

    // init cell state from c0 (deterministic per launch)
    cudaMemcpyAsync(c_ptr, c0, (size_t)BATCH * HDIM * sizeof(float),
                    cudaMemcpyDeviceToDevice);

    // Phase 1: gate preactivations
    {
        dim3 grid(HDIM / 64, (T_STEPS * BATCH) / 64, 4);
        xproj_kernel<<<grid, 256>>>(X, w_xi, w_xf, w_xo, w_xc, b_i, b_f, b_o, b_c);
    }

    // Phase 2: sequential scan; h state lives in the output rows
    for (int t = 0; t < T_STEPS; t++) {
        const float* h_prev = (t == 0) ? h0 : (out + (size_t)(t - 1) * BATCH * HDIM);
        float* h_out = out + (size_t)t * BATCH * HDIM;
        step_kernel<<<HDIM / 8, 256>>>(w_hi, w_hf, w_ho, w_hc, rr, h_prev, h_out, t);
    }

    // Phase 3: append h_T (= outs[T-1]) and c_T
    float* hT_dst = out + (size_t)T_STEPS * BATCH * HDIM;
    float* cT_dst = hT_dst + (size_t)BATCH * HDIM;
    cudaMemcpyAsync(hT_dst, out + (size_t)(T_STEPS - 1) * BATCH * HDIM,
                    (size_t)BATCH * HDIM * sizeof(float), cudaMemcpyDeviceToDevice);
    cudaMemcpyAsync(cT_dst, c_ptr,
                    (size_t)BATCH * HDIM * sizeof(float), cudaMemcpyDeviceToDevice);
}

// round 2
// speedup vs baseline: 1.5629x; 1.5629x over previous
#include <cuda_runtime.h>
#include <math.h>

// lpLSTM: T=512 steps, B=64 batch, IN=1024, H=1024.
// Output: outs [512,64,1024] ++ h_T [1,64,1024] ++ c_T [1,64,1024] (float32)

#define T_STEPS 512
#define BATCH   64
#define INDIM   1024
#define HDIM    1024
#define CTAS    128
#define NTHREADS 256
#define COLS_PER_CTA 8      // HDIM / CTAS
#define KCHUNK  128         // h k-chunk per smem stage
#define HPAD    132         // padded row stride for sh_h (conflict-free float4)

// Gate preactivation scratch: [gate][t][b][h] planes. 4 * 512*64*1024 fp32 = 512 MB.
__device__ float g_G[4ULL * T_STEPS * BATCH * HDIM];
// global barrier counter
__device__ unsigned g_bar;

// ---------------------------------------------------------------------------
// Kernel 1: x-projection GEMM.  G[g][m][n] = X[m,:] @ Wx_g[:,n] + b_g[n]
// (unchanged from R1 — known correct; tensor-core rewrite is next round)
// ---------------------------------------------------------------------------
__global__ __launch_bounds__(256) void xproj_kernel(
    const float* __restrict__ X,
    const float* __restrict__ Wi, const float* __restrict__ Wf,
    const float* __restrict__ Wo, const float* __restrict__ Wc,
    const float* __restrict__ bi, const float* __restrict__ bf,
    const float* __restrict__ bo, const float* __restrict__ bc)
{
    const int g = blockIdx.z;
    const float* W    = (g == 0) ? Wi : (g == 1) ? Wf : (g == 2) ? Wo : Wc;
    const float* bias = (g == 0) ? bi : (g == 1) ? bf : (g == 2) ? bo : bc;
    float* Cout = g_G + (size_t)g * T_STEPS * BATCH * HDIM;

    const int m0 = blockIdx.y * 64;
    const int n0 = blockIdx.x * 64;
    const int tid = threadIdx.x;
    const int tn = tid & 15;
    const int tm = tid >> 4;

    __shared__ float As[16][65];
    __shared__ float Bs[16][64];

    float acc[4][4];
#pragma unroll
    for (int i = 0; i < 4; i++)
#pragma unroll
        for (int j = 0; j < 4; j++) acc[i][j] = 0.0f;

    const int ar  = tid >> 2;
    const int ak  = (tid & 3) * 4;
    const int brr = tid >> 4;
    const int bc4 = (tid & 15) * 4;

    for (int k0 = 0; k0 < INDIM; k0 += 16) {
        float4 av = *(const float4*)(X + (size_t)(m0 + ar) * INDIM + k0 + ak);
        float4 bv = *(const float4*)(W + (size_t)(k0 + brr) * HDIM + n0 + bc4);
        As[ak + 0][ar] = av.x;
        As[ak + 1][ar] = av.y;
        As[ak + 2][ar] = av.z;
        As[ak + 3][ar] = av.w;
        *(float4*)&Bs[brr][bc4] = bv;
        __syncthreads();

#pragma unroll
        for (int k = 0; k < 16; k++) {
            float a0 = As[k][tm * 4 + 0];
            float a1 = As[k][tm * 4 + 1];
            float a2 = As[k][tm * 4 + 2];
            float a3 = As[k][tm * 4 + 3];
            float4 bb = *(float4*)&Bs[k][tn * 4];
            acc[0][0] += a0 * bb.x; acc[0][1] += a0 * bb.y; acc[0][2] += a0 * bb.z; acc[0][3] += a0 * bb.w;
            acc[1][0] += a1 * bb.x; acc[1][1] += a1 * bb.y; acc[1][2] += a1 * bb.z; acc[1][3] += a1 * bb.w;
            acc[2][0] += a2 * bb.x; acc[2][1] += a2 * bb.y; acc[2][2] += a2 * bb.z; acc[2][3] += a2 * bb.w;
            acc[3][0] += a3 * bb.x; acc[3][1] += a3 * bb.y; acc[3][2] += a3 * bb.z; acc[3][3] += a3 * bb.w;
        }
        __syncthreads();
    }

    const float b0 = bias[n0 + tn * 4 + 0];
    const float b1 = bias[n0 + tn * 4 + 1];
    const float b2 = bias[n0 + tn * 4 + 2];
    const float b3 = bias[n0 + tn * 4 + 3];
#pragma unroll
    for (int i = 0; i < 4; i++) {
        float4 v;
        v.x = acc[i][0] + b0;
        v.y = acc[i][1] + b1;
        v.z = acc[i][2] + b2;
        v.w = acc[i][3] + b3;
        *(float4*)(Cout + (size_t)(m0 + tm * 4 + i) * HDIM + n0 + tn * 4) = v;
    }
}

// ---------------------------------------------------------------------------
// Kernel 2: persistent recurrence. 128 CTAs (1/SM), weights resident in smem
// for all 512 steps, cell state in registers, software grid barrier per step.
//
// smem layout (dynamic):
//   w_s[g][hl][k] : 4 * 8 * 1024 floats = 128 KB  (k-contiguous -> LDS.128 broadcast)
//   sh_h[64][HPAD]: staged h_prev chunk, 64*132 floats = 33.8 KB
// total ~165 KB -> 1 CTA/SM.
// ---------------------------------------------------------------------------
__global__ __launch_bounds__(NTHREADS, 1) void scan_kernel(
    const float* __restrict__ Whi, const float* __restrict__ Whf,
    const float* __restrict__ Who, const float* __restrict__ Whc,
    const float* __restrict__ ret,
    const float* __restrict__ h0,
    const float* __restrict__ c0,
    float* __restrict__ out)
{
    extern __shared__ float smem[];
    float* w_s = smem;                                    // 4*8*1024
    float (*sh_h)[HPAD] = (float (*)[HPAD])(smem + 4 * COLS_PER_CTA * HDIM);

    const int tid   = threadIdx.x;
    const int b0    = tid & 31;          // batches b0, b0+32
    const int hl    = tid >> 5;          // 0..7 local h col
    const int hbase = blockIdx.x * COLS_PER_CTA;
    const int hcol  = hbase + hl;

    // ---- load recurrent weights once, transposed to [g][hl][k] ----
    {
        const float* Ws[4] = {Whi, Whf, Who, Whc};
        for (int i = tid; i < 4 * HDIM * 2; i += NTHREADS) {
            int g    = i >> 11;            // / 2048
            int rem  = i & 2047;
            int k    = rem >> 1;
            int half = (rem & 1) * 4;
            float4 v = *(const float4*)(Ws[g] + (size_t)k * HDIM + hbase + half);
            w_s[((g * COLS_PER_CTA + half + 0) << 10) + k] = v.x;
            w_s[((g * COLS_PER_CTA + half + 1) << 10) + k] = v.y;
            w_s[((g * COLS_PER_CTA + half + 2) << 10) + k] = v.z;
            w_s[((g * COLS_PER_CTA + half + 3) << 10) + k] = v.w;
        }
    }

    const float* wpi = w_s + ((0 * COLS_PER_CTA + hl) << 10);
    const float* wpf = w_s + ((1 * COLS_PER_CTA + hl) << 10);
    const float* wpo = w_s + ((2 * COLS_PER_CTA + hl) << 10);
    const float* wpc = w_s + ((3 * COLS_PER_CTA + hl) << 10);

    const size_t idx0 = (size_t)b0 * HDIM + hcol;
    const size_t idx1 = (size_t)(b0 + 32) * HDIM + hcol;

    float c_reg0 = c0[idx0];
    float c_reg1 = c0[idx1];
    const float r = ret[hcol];
    const size_t plane = (size_t)T_STEPS * BATCH * HDIM;

    __syncthreads();

    for (int t = 0; t < T_STEPS; t++) {
        const float* h_prev = (t == 0) ? h0 : (out + (size_t)(t - 1) * BATCH * HDIM);
        float* h_out = out + (size_t)t * BATCH * HDIM;

        float a00 = 0.f, a01 = 0.f, a02 = 0.f, a03 = 0.f;
        float a10 = 0.f, a11 = 0.f, a12 = 0.f, a13 = 0.f;

        for (int k0 = 0; k0 < HDIM; k0 += KCHUNK) {
            // stage h chunk: 64 rows x 128 cols, 8 float4 per thread, L2-coherent
#pragma unroll
            for (int j = 0; j < 8; j++) {
                int idx = j * NTHREADS + tid;
                int row = idx >> 5;
                int c4  = (idx & 31) * 4;
                float4 v = __ldcg((const float4*)(h_prev + (size_t)row * HDIM + k0 + c4));
                *(float4*)&sh_h[row][c4] = v;
            }
            __syncthreads();

#pragma unroll 8
            for (int k = 0; k < KCHUNK; k += 4) {
                float4 hv0 = *(const float4*)&sh_h[b0][k];
                float4 hv1 = *(const float4*)&sh_h[b0 + 32][k];
                float4 wi = *(const float4*)(wpi + k0 + k);
                float4 wf = *(const float4*)(wpf + k0 + k);
                float4 wo = *(const float4*)(wpo + k0 + k);
                float4 wc = *(const float4*)(wpc + k0 + k);

                a00 += hv0.x * wi.x; a01 += hv0.x * wf.x; a02 += hv0.x * wo.x; a03 += hv0.x * wc.x;
                a10 += hv1.x * wi.x; a11 += hv1.x * wf.x; a12 += hv1.x * wo.x; a13 += hv1.x * wc.x;
                a00 += hv0.y * wi.y; a01 += hv0.y * wf.y; a02 += hv0.y * wo.y; a03 += hv0.y * wc.y;
                a10 += hv1.y * wi.y; a11 += hv1.y * wf.y; a12 += hv1.y * wo.y; a13 += hv1.y * wc.y;
                a00 += hv0.z * wi.z; a01 += hv0.z * wf.z; a02 += hv0.z * wo.z; a03 += hv0.z * wc.z;
                a10 += hv1.z * wi.z; a11 += hv1.z * wf.z; a12 += hv1.z * wo.z; a13 += hv1.z * wc.z;
                a00 += hv0.w * wi.w; a01 += hv0.w * wf.w; a02 += hv0.w * wo.w; a03 += hv0.w * wc.w;
                a10 += hv1.w * wi.w; a11 += hv1.w * wf.w; a12 += hv1.w * wo.w; a13 += hv1.w * wc.w;
            }
            __syncthreads();
        }

        // ---- elementwise LSTM + retention blend ----
        const float* Gt = g_G + (size_t)t * BATCH * HDIM;
        {
            float gi = Gt[0 * plane + idx0] + a00;
            float gf = Gt[1 * plane + idx0] + a01;
            float go = Gt[2 * plane + idx0] + a02;
            float gc = Gt[3 * plane + idx0] + a03;
            float i_t = 1.0f / (1.0f + __expf(-gi));
            float f_t = 1.0f / (1.0f + __expf(-gf));
            float o_t = 1.0f / (1.0f + __expf(-go));
            float g_t = tanhf(gc);
            c_reg0 = c_reg0 * f_t + i_t * g_t;
            float h_lstm = o_t * tanhf(c_reg0);
            float hp = __ldcg(h_prev + idx0);
            h_out[idx0] = r * hp + (1.0f - r) * h_lstm;
        }
        {
            float gi = Gt[0 * plane + idx1] + a10;
            float gf = Gt[1 * plane + idx1] + a11;
            float go = Gt[2 * plane + idx1] + a12;
            float gc = Gt[3 * plane + idx1] + a13;
            float i_t = 1.0f / (1.0f + __expf(-gi));
            float f_t = 1.0f / (1.0f + __expf(-gf));
            float o_t = 1.0f / (1.0f + __expf(-go));
            float g_t = tanhf(gc);
            c_reg1 = c_reg1 * f_t + i_t * g_t;
            float h_lstm = o_t * tanhf(c_reg1);
            float hp = __ldcg(h_prev + idx1);
            h_out[idx1] = r * hp + (1.0f - r) * h_lstm;
        }

        // ---- global barrier ----
        __threadfence();
        __syncthreads();
        if (tid == 0) {
            atomicAdd(&g_bar, 1u);
            volatile unsigned* bar = &g_bar;
            unsigned target = (unsigned)(t + 1) * CTAS;
            while (*bar < target) { __nanosleep(64); }
        }
        __syncthreads();
    }

    // ---- tail: h_T and c_T ----
    {
        float* hT = out + (size_t)T_STEPS * BATCH * HDIM;
        float* cT = hT + (size_t)BATCH * HDIM;
        const float* hlast = out + (size_t)(T_STEPS - 1) * BATCH * HDIM;
        hT[idx0] = __ldcg(hlast + idx0);
        hT[idx1] = __ldcg(hlast + idx1);
        cT[idx0] = c_reg0;
        cT[idx1] = c_reg1;
    }
}

// ---------------------------------------------------------------------------
extern "C" void kernel_launch(void* const* d_in, const int* in_sizes, int n_in,
                              void* d_out, int out_size)
{
    const float* X    = (const float*)d_in[0];
    const float* h0   = (const float*)d_in[1];
    const float* c0   = (const float*)d_in[2];
    const float* w_xi = (const float*)d_in[3];
    const float* w_xf = (const float*)d_in[4];
    const float* w_xo = (const float*)d_in[5];
    const float* w_xc = (const float*)d_in[6];
    const float* w_hi = (const float*)d_in[7];
    const float* w_hf = (const float*)d_in[8];
    const float* w_ho = (const float*)d_in[9];
    const float* w_hc = (const float*)d_in[10];
    const float* b_i  = (const float*)d_in[11];
    const float* b_f  = (const float*)d_in[12];
    const float* b_o  = (const float*)d_in[13];
    const float* b_c  = (const float*)d_in[14];
    const float* rr   = (const float*)d_in[15];

    float* out = (float*)d_out;

    // reset global barrier counter (graph-replay safe)
    void* bar_ptr = nullptr;
    cudaGetSymbolAddress(&bar_ptr, g_bar);
    cudaMemsetAsync(bar_ptr, 0, sizeof(unsigned));

    // Phase 1: gate preactivations
    {
        dim3 grid(HDIM / 64, (T_STEPS * BATCH) / 64, 4);
        xproj_kernel<<<grid, 256>>>(X, w_xi, w_xf, w_xo, w_xc, b_i, b_f, b_o, b_c);
    }

    // Phase 2: persistent scan
    {
        const int smem_bytes = (4 * COLS_PER_CTA * HDIM + BATCH * HPAD) * sizeof(float);
        static int attr_set = 0;
        if (!attr_set) {
            cudaFuncSetAttribute(scan_kernel,
                                 cudaFuncAttributeMaxDynamicSharedMemorySize, smem_bytes);
            attr_set = 1;
        }
        scan_kernel<<<CTAS, NTHREADS, smem_bytes>>>(
            w_hi, w_hf, w_ho, w_hc, rr, h0, c0, out);
    }
}

// round 5
// speedup vs baseline: 2.0894x; 1.3369x over previous
#include <cuda_runtime.h>
#include <cuda_bf16.h>
#include <stdint.h>
#include <math.h>

// lpLSTM: T=512, B=64, IN=H=1024.
// Output: outs [512,64,1024] ++ h_T [1,64,1024] ++ c_T [1,64,1024] (float32)

#define T_STEPS 512
#define BATCH   64
#define INDIM   1024
#define HDIM    1024
#define CTAS    128
#define NTHREADS 256
#define COLS_PER_CTA 8
#define KCHUNK  128
#define HPAD    132

// ---------------- scratch (static device memory; allowed) ----------------
__device__ float g_G[4ULL * T_STEPS * BATCH * HDIM];              // 512 MB
__device__ unsigned g_bar;
__device__ __nv_bfloat16 g_Xhi[(size_t)T_STEPS * BATCH * INDIM];  // 64 MB
__device__ __nv_bfloat16 g_Xlo[(size_t)T_STEPS * BATCH * INDIM];  // 64 MB
__device__ __nv_bfloat16 g_Whi[4][(size_t)HDIM * INDIM];          // [gate][N][K]
__device__ __nv_bfloat16 g_Wlo[4][(size_t)HDIM * INDIM];

// ---------------- PTX helpers (all sm_80-compatible) ----------------
__device__ __forceinline__ uint32_t smem_u32(const void* p) {
    uint32_t a;
    asm("{ .reg .u64 t; cvta.to.shared.u64 t, %1; cvt.u32.u64 %0, t; }" : "=r"(a) : "l"(p));
    return a;
}
#define CP_ASYNC16(sa, gp) \
    asm volatile("cp.async.cg.shared.global [%0], [%1], 16;" :: "r"(sa), "l"(gp))
#define CP_COMMIT() asm volatile("cp.async.commit_group;" ::: "memory")
#define CP_WAIT(n)  asm volatile("cp.async.wait_group %0;" :: "n"(n) : "memory")

#define LDSM_X4(r0, r1, r2, r3, a) \
    asm volatile("ldmatrix.sync.aligned.m8n8.x4.shared.b16 {%0,%1,%2,%3}, [%4];" \
        : "=r"(r0), "=r"(r1), "=r"(r2), "=r"(r3) : "r"(a))
#define LDSM_X2(r0, r1, a) \
    asm volatile("ldmatrix.sync.aligned.m8n8.x2.shared.b16 {%0,%1}, [%2];" \
        : "=r"(r0), "=r"(r1) : "r"(a))
#define MMA16816(d, a, b) \
    asm volatile("mma.sync.aligned.m16n8k16.row.col.f32.bf16.bf16.f32 " \
        "{%0,%1,%2,%3},{%4,%5,%6,%7},{%8,%9},{%0,%1,%2,%3};" \
        : "+f"((d)[0]), "+f"((d)[1]), "+f"((d)[2]), "+f"((d)[3]) \
        : "r"((a)[0]), "r"((a)[1]), "r"((a)[2]), "r"((a)[3]), "r"((b)[0]), "r"((b)[1]))

// ---------------------------------------------------------------------------
// Prep 1: split X into bf16 hi/lo
// ---------------------------------------------------------------------------
__global__ __launch_bounds__(256) void xsplit_kernel(const float* __restrict__ X) {
    size_t i = (size_t)blockIdx.x * blockDim.x + threadIdx.x;   // over float4s
    float4 v = ((const float4*)X)[i];
    __nv_bfloat16 h0 = __float2bfloat16_rn(v.x);
    __nv_bfloat16 h1 = __float2bfloat16_rn(v.y);
    __nv_bfloat16 h2 = __float2bfloat16_rn(v.z);
    __nv_bfloat16 h3 = __float2bfloat16_rn(v.w);
    __nv_bfloat16 l0 = __float2bfloat16_rn(v.x - __bfloat162float(h0));
    __nv_bfloat16 l1 = __float2bfloat16_rn(v.y - __bfloat162float(h1));
    __nv_bfloat16 l2 = __float2bfloat16_rn(v.z - __bfloat162float(h2));
    __nv_bfloat16 l3 = __float2bfloat16_rn(v.w - __bfloat162float(h3));
    __nv_bfloat162* ph = (__nv_bfloat162*)g_Xhi;
    __nv_bfloat162* pl = (__nv_bfloat162*)g_Xlo;
    ph[2 * i]     = __nv_bfloat162(h0, h1);
    ph[2 * i + 1] = __nv_bfloat162(h2, h3);
    pl[2 * i]     = __nv_bfloat162(l0, l1);
    pl[2 * i + 1] = __nv_bfloat162(l2, l3);
}

// ---------------------------------------------------------------------------
// Prep 2: transpose W [K,H] -> [H,K] = [N][K] and split hi/lo, per gate
// ---------------------------------------------------------------------------
__global__ void wprep_kernel(const float* __restrict__ Wi, const float* __restrict__ Wf,
                             const float* __restrict__ Wo, const float* __restrict__ Wc) {
    __shared__ float tile[32][33];
    const int g = blockIdx.z;
    const float* W = (g == 0) ? Wi : (g == 1) ? Wf : (g == 2) ? Wo : Wc;
    const int n  = blockIdx.x * 32 + threadIdx.x;
    const int k0 = blockIdx.y * 32;
#pragma unroll
    for (int i = 0; i < 32; i += 8)
        tile[threadIdx.y + i][threadIdx.x] = W[(size_t)(k0 + threadIdx.y + i) * HDIM + n];
    __syncthreads();
    const int kk = k0 + threadIdx.x;
    const int nn = blockIdx.x * 32 + threadIdx.y;
#pragma unroll
    for (int i = 0; i < 32; i += 8) {
        float v = tile[threadIdx.x][threadIdx.y + i];
        __nv_bfloat16 hi = __float2bfloat16_rn(v);
        __nv_bfloat16 lo = __float2bfloat16_rn(v - __bfloat162float(hi));
        size_t o = (size_t)(nn + i) * INDIM + kk;
        g_Whi[g][o] = hi;
        g_Wlo[g][o] = lo;
    }
}

// ---------------------------------------------------------------------------
// Kernel 1: x-projection via mma.sync bf16x3 (HMMA).
// CTA tile 128x128, 8 warps (2x4), warp tile 64x32, BK=32, cp.async 2-stage.
// smem per stage: Ah(10240) Al(10240) Bh(10240) Bl(10240) = 40960 B; x2 stages.
// Row stride = 40 bf16 (80 B): 16B-aligned, conflict-free for ldmatrix.
// ---------------------------------------------------------------------------
#define XP_BK      32
#define XP_NCHUNK  (INDIM / XP_BK)
#define XP_STRIDE  40                      // bf16 elements per row
#define XP_MATSZ   (128 * XP_STRIDE * 2)   // 10240 bytes
#define XP_STAGE   (4 * XP_MATSZ)          // 40960
#define XP_SMEM    (2 * XP_STAGE)          // 81920

__global__ __launch_bounds__(256) void xproj_mma_kernel(
    const float* __restrict__ bi, const float* __restrict__ bf_,
    const float* __restrict__ bo, const float* __restrict__ bc)
{
    extern __shared__ char smem[];
    const uint32_t sb = smem_u32(smem);
    const int g   = blockIdx.z;
    const int n0  = blockIdx.x * 128;
    const int m0  = blockIdx.y * 128;
    const int tid = threadIdx.x;
    const int wid = tid >> 5;
    const int lane = tid & 31;
    const int warp_m = (wid >> 2) * 64;   // 0 or 64
    const int warp_n = (wid & 3) * 32;    // 0,32,64,96

    const float* bias = (g == 0) ? bi : (g == 1) ? bf_ : (g == 2) ? bo : bc;
    const __nv_bfloat16* Xh = g_Xhi;
    const __nv_bfloat16* Xl = g_Xlo;
    const __nv_bfloat16* Wh = g_Whi[g];
    const __nv_bfloat16* Wl = g_Wlo[g];

    // per-thread load mapping: idx j*256+tid -> row=idx>>2, seg=idx&3 (16B)
    const int lr  = tid >> 2;        // row for j=0 (0..63); j=1 adds 64
    const int lsg = tid & 3;         // 16B segment (k offset seg*8)

    float acc[2][4][4];              // [mi/2? no: 4 m-tiles][4 n-tiles][4]
    // NOTE: 4 m-tiles x 4 n-tiles x 4 = 64 floats
    float a_cc[4][4][4];
#pragma unroll
    for (int mi = 0; mi < 4; mi++)
#pragma unroll
        for (int ni = 0; ni < 4; ni++)
#pragma unroll
            for (int q = 0; q < 4; q++) a_cc[mi][ni][q] = 0.0f;
    (void)acc;

    // issue loads for chunk kc into stage buffer
    auto load_chunk = [&](int kc, int stg) {
        const int kg = kc * XP_BK;
        const uint32_t base = sb + stg * XP_STAGE;
#pragma unroll
        for (int j = 0; j < 2; j++) {
            const int r = lr + j * 64;
            const uint32_t so = (uint32_t)(r * (XP_STRIDE * 2) + lsg * 16);
            const size_t ga = (size_t)(m0 + r) * INDIM + kg + lsg * 8;
            const size_t gb = (size_t)(n0 + r) * INDIM + kg + lsg * 8;
            CP_ASYNC16(base + so,                 Xh + ga);
            CP_ASYNC16(base + XP_MATSZ + so,      Xl + ga);
            CP_ASYNC16(base + 2 * XP_MATSZ + so,  Wh + gb);
            CP_ASYNC16(base + 3 * XP_MATSZ + so,  Wl + gb);
        }
        CP_COMMIT();
    };

    load_chunk(0, 0);

    // ldmatrix address components (constant across chunks)
    const uint32_t a_row = (uint32_t)(warp_m + (lane & 15));
    const uint32_t a_coff = (uint32_t)((lane >> 4) * 8);
    const uint32_t b_row0 = (uint32_t)(warp_n + (lane & 7));
    const uint32_t b_coff = (uint32_t)(((lane >> 3) & 1) * 8);

    for (int kc = 0; kc < XP_NCHUNK; kc++) {
        const int stg = kc & 1;
        if (kc + 1 < XP_NCHUNK) {
            load_chunk(kc + 1, stg ^ 1);
            CP_WAIT(1);
        } else {
            CP_WAIT(0);
        }
        __syncthreads();

        const uint32_t base = sb + stg * XP_STAGE;
#pragma unroll
        for (int ks = 0; ks < 2; ks++) {
            uint32_t ah[4][4], al[4][4], bh[4][2], bl[4][2];
#pragma unroll
            for (int mi = 0; mi < 4; mi++) {
                uint32_t addr = base +
                    (a_row + mi * 16) * (XP_STRIDE * 2) + (ks * 16 + a_coff) * 2;
                LDSM_X4(ah[mi][0], ah[mi][1], ah[mi][2], ah[mi][3], addr);
                LDSM_X4(al[mi][0], al[mi][1], al[mi][2], al[mi][3], addr + XP_MATSZ);
            }
#pragma unroll
            for (int ni = 0; ni < 4; ni++) {
                uint32_t addr = base + 2 * XP_MATSZ +
                    (b_row0 + ni * 8) * (XP_STRIDE * 2) + (ks * 16 + b_coff) * 2;
                LDSM_X2(bh[ni][0], bh[ni][1], addr);
                LDSM_X2(bl[ni][0], bl[ni][1], addr + XP_MATSZ);
            }
#pragma unroll
            for (int mi = 0; mi < 4; mi++)
#pragma unroll
                for (int ni = 0; ni < 4; ni++) {
                    MMA16816(a_cc[mi][ni], ah[mi], bh[ni]);
                    MMA16816(a_cc[mi][ni], ah[mi], bl[ni]);
                    MMA16816(a_cc[mi][ni], al[mi], bh[ni]);
                }
        }
        __syncthreads();
    }

    // epilogue: add bias, store fp32 to g_G
    float* Gg = g_G + (size_t)g * T_STEPS * BATCH * HDIM;
    const int col_base = n0 + warp_n + 2 * (lane & 3);
    const int row_base = m0 + warp_m + (lane >> 2);
    float bv0[4], bv1[4];
#pragma unroll
    for (int ni = 0; ni < 4; ni++) {
        bv0[ni] = __ldg(bias + col_base + ni * 8);
        bv1[ni] = __ldg(bias + col_base + ni * 8 + 1);
    }
#pragma unroll
    for (int mi = 0; mi < 4; mi++) {
        const int r0 = row_base + mi * 16;
#pragma unroll
        for (int ni = 0; ni < 4; ni++) {
            const int c = col_base + ni * 8;
            float2 v0 = make_float2(a_cc[mi][ni][0] + bv0[ni], a_cc[mi][ni][1] + bv1[ni]);
            float2 v1 = make_float2(a_cc[mi][ni][2] + bv0[ni], a_cc[mi][ni][3] + bv1[ni]);
            *(float2*)(Gg + (size_t)r0 * HDIM + c)       = v0;
            *(float2*)(Gg + (size_t)(r0 + 8) * HDIM + c) = v1;
        }
    }
}

// ---------------------------------------------------------------------------
// Kernel 2: persistent recurrence (unchanged from R2).
// ---------------------------------------------------------------------------
__global__ __launch_bounds__(NTHREADS, 1) void scan_kernel(
    const float* __restrict__ Whi, const float* __restrict__ Whf,
    const float* __restrict__ Who, const float* __restrict__ Whc,
    const float* __restrict__ ret,
    const float* __restrict__ h0,
    const float* __restrict__ c0,
    float* __restrict__ out)
{
    extern __shared__ float smemf[];
    float* w_s = smemf;
    float (*sh_h)[HPAD] = (float (*)[HPAD])(smemf + 4 * COLS_PER_CTA * HDIM);

    const int tid   = threadIdx.x;
    const int b0    = tid & 31;
    const int hl    = tid >> 5;
    const int hbase = blockIdx.x * COLS_PER_CTA;
    const int hcol  = hbase + hl;

    {
        const float* Ws[4] = {Whi, Whf, Who, Whc};
        for (int i = tid; i < 4 * HDIM * 2; i += NTHREADS) {
            int g = i >> 11, rem = i & 2047, k = rem >> 1, half = (rem & 1) * 4;
            float4 v = *(const float4*)(Ws[g] + (size_t)k * HDIM + hbase + half);
            w_s[((g * COLS_PER_CTA + half + 0) << 10) + k] = v.x;
            w_s[((g * COLS_PER_CTA + half + 1) << 10) + k] = v.y;
            w_s[((g * COLS_PER_CTA + half + 2) << 10) + k] = v.z;
            w_s[((g * COLS_PER_CTA + half + 3) << 10) + k] = v.w;
        }
    }
    const float* wpi = w_s + ((0 * COLS_PER_CTA + hl) << 10);
    const float* wpf = w_s + ((1 * COLS_PER_CTA + hl) << 10);
    const float* wpo = w_s + ((2 * COLS_PER_CTA + hl) << 10);
    const float* wpc = w_s + ((3 * COLS_PER_CTA + hl) << 10);

    const size_t idx0 = (size_t)b0 * HDIM + hcol;
    const size_t idx1 = (size_t)(b0 + 32) * HDIM + hcol;
    float c_reg0 = c0[idx0];
    float c_reg1 = c0[idx1];
    const float r = ret[hcol];
    const size_t plane = (size_t)T_STEPS * BATCH * HDIM;

    __syncthreads();

    for (int t = 0; t < T_STEPS; t++) {
        const float* h_prev = (t == 0) ? h0 : (out + (size_t)(t - 1) * BATCH * HDIM);
        float* h_out = out + (size_t)t * BATCH * HDIM;

        float a00 = 0.f, a01 = 0.f, a02 = 0.f, a03 = 0.f;
        float a10 = 0.f, a11 = 0.f, a12 = 0.f, a13 = 0.f;

        for (int k0 = 0; k0 < HDIM; k0 += KCHUNK) {
#pragma unroll
            for (int j = 0; j < 8; j++) {
                int idx = j * NTHREADS + tid;
                int row = idx >> 5;
                int c4  = (idx & 31) * 4;
                float4 v = __ldcg((const float4*)(h_prev + (size_t)row * HDIM + k0 + c4));
                *(float4*)&sh_h[row][c4] = v;
            }
            __syncthreads();

#pragma unroll 8
            for (int k = 0; k < KCHUNK; k += 4) {
                float4 hv0 = *(const float4*)&sh_h[b0][k];
                float4 hv1 = *(const float4*)&sh_h[b0 + 32][k];
                float4 wi = *(const float4*)(wpi + k0 + k);
                float4 wf = *(const float4*)(wpf + k0 + k);
                float4 wo = *(const float4*)(wpo + k0 + k);
                float4 wc = *(const float4*)(wpc + k0 + k);
                a00 += hv0.x * wi.x; a01 += hv0.x * wf.x; a02 += hv0.x * wo.x; a03 += hv0.x * wc.x;
                a10 += hv1.x * wi.x; a11 += hv1.x * wf.x; a12 += hv1.x * wo.x; a13 += hv1.x * wc.x;
                a00 += hv0.y * wi.y; a01 += hv0.y * wf.y; a02 += hv0.y * wo.y; a03 += hv0.y * wc.y;
                a10 += hv1.y * wi.y; a11 += hv1.y * wf.y; a12 += hv1.y * wo.y; a13 += hv1.y * wc.y;
                a00 += hv0.z * wi.z; a01 += hv0.z * wf.z; a02 += hv0.z * wo.z; a03 += hv0.z * wc.z;
                a10 += hv1.z * wi.z; a11 += hv1.z * wf.z; a12 += hv1.z * wo.z; a13 += hv1.z * wc.z;
                a00 += hv0.w * wi.w; a01 += hv0.w * wf.w; a02 += hv0.w * wo.w; a03 += hv0.w * wc.w;
                a10 += hv1.w * wi.w; a11 += hv1.w * wf.w; a12 += hv1.w * wo.w; a13 += hv1.w * wc.w;
            }
            __syncthreads();
        }

        const float* Gt = g_G + (size_t)t * BATCH * HDIM;
        {
            float gi = Gt[0 * plane + idx0] + a00;
            float gf = Gt[1 * plane + idx0] + a01;
            float go = Gt[2 * plane + idx0] + a02;
            float gc = Gt[3 * plane + idx0] + a03;
            float i_t = 1.0f / (1.0f + __expf(-gi));
            float f_t = 1.0f / (1.0f + __expf(-gf));
            float o_t = 1.0f / (1.0f + __expf(-go));
            float g_t = tanhf(gc);
            c_reg0 = c_reg0 * f_t + i_t * g_t;
            float h_lstm = o_t * tanhf(c_reg0);
            float hp = __ldcg(h_prev + idx0);
            h_out[idx0] = r * hp + (1.0f - r) * h_lstm;
        }
        {
            float gi = Gt[0 * plane + idx1] + a10;
            float gf = Gt[1 * plane + idx1] + a11;
            float go = Gt[2 * plane + idx1] + a12;
            float gc = Gt[3 * plane + idx1] + a13;
            float i_t = 1.0f / (1.0f + __expf(-gi));
            float f_t = 1.0f / (1.0f + __expf(-gf));
            float o_t = 1.0f / (1.0f + __expf(-go));
            float g_t = tanhf(gc);
            c_reg1 = c_reg1 * f_t + i_t * g_t;
            float h_lstm = o_t * tanhf(c_reg1);
            float hp = __ldcg(h_prev + idx1);
            h_out[idx1] = r * hp + (1.0f - r) * h_lstm;
        }

        __threadfence();
        __syncthreads();
        if (tid == 0) {
            atomicAdd(&g_bar, 1u);
            volatile unsigned* bar = &g_bar;
            unsigned target = (unsigned)(t + 1) * CTAS;
            while (*bar < target) { __nanosleep(64); }
        }
        __syncthreads();
    }

    {
        float* hT = out + (size_t)T_STEPS * BATCH * HDIM;
        float* cT = hT + (size_t)BATCH * HDIM;
        const float* hlast = out + (size_t)(T_STEPS - 1) * BATCH * HDIM;
        hT[idx0] = __ldcg(hlast + idx0);
        hT[idx1] = __ldcg(hlast + idx1);
        cT[idx0] = c_reg0;
        cT[idx1] = c_reg1;
    }
}

// ---------------------------------------------------------------------------
extern "C" void kernel_launch(void* const* d_in, const int* in_sizes, int n_in,
                              void* d_out, int out_size)
{
    const float* X    = (const float*)d_in[0];
    const float* h0   = (const float*)d_in[1];
    const float* c0   = (const float*)d_in[2];
    const float* w_xi = (const float*)d_in[3];
    const float* w_xf = (const float*)d_in[4];
    const float* w_xo = (const float*)d_in[5];
    const float* w_xc = (const float*)d_in[6];
    const float* w_hi = (const float*)d_in[7];
    const float* w_hf = (const float*)d_in[8];
    const float* w_ho = (const float*)d_in[9];
    const float* w_hc = (const float*)d_in[10];
    const float* b_i  = (const float*)d_in[11];
    const float* b_f  = (const float*)d_in[12];
    const float* b_o  = (const float*)d_in[13];
    const float* b_c  = (const float*)d_in[14];
    const float* rr   = (const float*)d_in[15];

    float* out = (float*)d_out;

    void* bar_ptr = nullptr;
    cudaGetSymbolAddress(&bar_ptr, g_bar);
    cudaMemsetAsync(bar_ptr, 0, sizeof(unsigned));

    static int attr_set = 0;
    const int smem_scan = (4 * COLS_PER_CTA * HDIM + BATCH * HPAD) * sizeof(float);
    if (!attr_set) {
        cudaFuncSetAttribute(scan_kernel,
                             cudaFuncAttributeMaxDynamicSharedMemorySize, smem_scan);
        cudaFuncSetAttribute(xproj_mma_kernel,
                             cudaFuncAttributeMaxDynamicSharedMemorySize, XP_SMEM);
        attr_set = 1;
    }

    // Prep: bf16 hi/lo splits
    xsplit_kernel<<<(T_STEPS * BATCH * INDIM) / (4 * 256), 256>>>(X);
    wprep_kernel<<<dim3(32, 32, 4), dim3(32, 8)>>>(w_xi, w_xf, w_xo, w_xc);

    // Phase 1: gate preactivations via mma.sync bf16x3
    {
        dim3 grid(HDIM / 128, (T_STEPS * BATCH) / 128, 4);
        xproj_mma_kernel<<<grid, 256, XP_SMEM>>>(b_i, b_f, b_o, b_c);
    }

    // Phase 2: persistent scan
    scan_kernel<<<CTAS, NTHREADS, smem_scan>>>(w_hi, w_hf, w_ho, w_hc, rr, h0, c0, out);
}

// round 6
// speedup vs baseline: 4.3306x; 2.0726x over previous
#include <cuda_runtime.h>
#include <cuda_bf16.h>
#include <stdint.h>
#include <math.h>

// lpLSTM: T=512, B=64, IN=H=1024.
// Output: outs [512,64,1024] ++ h_T [1,64,1024] ++ c_T [1,64,1024] (float32)

#define T_STEPS 512
#define BATCH   64
#define INDIM   1024
#define HDIM    1024
#define CTAS    128

// ---------------- scratch (static device memory; allowed) ----------------
__device__ float g_G[4ULL * T_STEPS * BATCH * HDIM];              // 512 MB
__device__ unsigned g_bar;
__device__ __nv_bfloat16 g_Xhi[(size_t)T_STEPS * BATCH * INDIM];  // 64 MB
__device__ __nv_bfloat16 g_Xlo[(size_t)T_STEPS * BATCH * INDIM];  // 64 MB
__device__ __nv_bfloat16 g_Wxhi[4ULL * HDIM * INDIM];             // [g][n][k] 8 MB
__device__ __nv_bfloat16 g_Wxlo[4ULL * HDIM * INDIM];
__device__ __nv_bfloat16 g_Whhi[4ULL * HDIM * INDIM];             // recurrent [g][n][k]
__device__ __nv_bfloat16 g_Whlo[4ULL * HDIM * INDIM];
__device__ __nv_bfloat16 g_hhi[BATCH * HDIM];                     // per-step h state (hi)
__device__ __nv_bfloat16 g_hlo[BATCH * HDIM];                     // per-step h state (lo)

// ---------------- PTX helpers (sm_80-compatible) ----------------
__device__ __forceinline__ uint32_t smem_u32(const void* p) {
    uint32_t a;
    asm("{ .reg .u64 t; cvta.to.shared.u64 t, %1; cvt.u32.u64 %0, t; }" : "=r"(a) : "l"(p));
    return a;
}
#define CP_ASYNC16(sa, gp) \
    asm volatile("cp.async.cg.shared.global [%0], [%1], 16;" :: "r"(sa), "l"(gp))
#define CP_COMMIT() asm volatile("cp.async.commit_group;" ::: "memory")
#define CP_WAIT(n)  asm volatile("cp.async.wait_group %0;" :: "n"(n) : "memory")

#define LDSM_X4(r0, r1, r2, r3, a) \
    asm volatile("ldmatrix.sync.aligned.m8n8.x4.shared.b16 {%0,%1,%2,%3}, [%4];" \
        : "=r"(r0), "=r"(r1), "=r"(r2), "=r"(r3) : "r"(a))
#define LDSM_X2(r0, r1, a) \
    asm volatile("ldmatrix.sync.aligned.m8n8.x2.shared.b16 {%0,%1}, [%2];" \
        : "=r"(r0), "=r"(r1) : "r"(a))
#define MMA16816(d, a, b) \
    asm volatile("mma.sync.aligned.m16n8k16.row.col.f32.bf16.bf16.f32 " \
        "{%0,%1,%2,%3},{%4,%5,%6,%7},{%8,%9},{%0,%1,%2,%3};" \
        : "+f"((d)[0]), "+f"((d)[1]), "+f"((d)[2]), "+f"((d)[3]) \
        : "r"((a)[0]), "r"((a)[1]), "r"((a)[2]), "r"((a)[3]), "r"((b)[0]), "r"((b)[1]))

// ---------------------------------------------------------------------------
// Prep 1: split X into bf16 hi/lo
// ---------------------------------------------------------------------------
__global__ __launch_bounds__(256) void xsplit_kernel(const float* __restrict__ X) {
    size_t i = (size_t)blockIdx.x * blockDim.x + threadIdx.x;
    float4 v = ((const float4*)X)[i];
    __nv_bfloat16 h0 = __float2bfloat16_rn(v.x);
    __nv_bfloat16 h1 = __float2bfloat16_rn(v.y);
    __nv_bfloat16 h2 = __float2bfloat16_rn(v.z);
    __nv_bfloat16 h3 = __float2bfloat16_rn(v.w);
    __nv_bfloat16 l0 = __float2bfloat16_rn(v.x - __bfloat162float(h0));
    __nv_bfloat16 l1 = __float2bfloat16_rn(v.y - __bfloat162float(h1));
    __nv_bfloat16 l2 = __float2bfloat16_rn(v.z - __bfloat162float(h2));
    __nv_bfloat16 l3 = __float2bfloat16_rn(v.w - __bfloat162float(h3));
    __nv_bfloat162* ph = (__nv_bfloat162*)g_Xhi;
    __nv_bfloat162* pl = (__nv_bfloat162*)g_Xlo;
    ph[2 * i]     = __nv_bfloat162(h0, h1);
    ph[2 * i + 1] = __nv_bfloat162(h2, h3);
    pl[2 * i]     = __nv_bfloat162(l0, l1);
    pl[2 * i + 1] = __nv_bfloat162(l2, l3);
}

// ---------------------------------------------------------------------------
// Prep 2: transpose W [K,H] -> [N][K] and split hi/lo, per gate (generic dst)
// ---------------------------------------------------------------------------
__global__ void wprep_kernel(const float* __restrict__ Wi, const float* __restrict__ Wf,
                             const float* __restrict__ Wo, const float* __restrict__ Wc,
                             __nv_bfloat16* __restrict__ dsthi,
                             __nv_bfloat16* __restrict__ dstlo) {
    __shared__ float tile[32][33];
    const int g = blockIdx.z;
    const float* W = (g == 0) ? Wi : (g == 1) ? Wf : (g == 2) ? Wo : Wc;
    const int n  = blockIdx.x * 32 + threadIdx.x;
    const int k0 = blockIdx.y * 32;
#pragma unroll
    for (int i = 0; i < 32; i += 8)
        tile[threadIdx.y + i][threadIdx.x] = W[(size_t)(k0 + threadIdx.y + i) * HDIM + n];
    __syncthreads();
    const int kk = k0 + threadIdx.x;
    const int nn = blockIdx.x * 32 + threadIdx.y;
#pragma unroll
    for (int i = 0; i < 32; i += 8) {
        float v = tile[threadIdx.x][threadIdx.y + i];
        __nv_bfloat16 hi = __float2bfloat16_rn(v);
        __nv_bfloat16 lo = __float2bfloat16_rn(v - __bfloat162float(hi));
        size_t o = (size_t)g * HDIM * INDIM + (size_t)(nn + i) * INDIM + kk;
        dsthi[o] = hi;
        dstlo[o] = lo;
    }
}

// ---------------------------------------------------------------------------
// Kernel 1: x-projection via mma.sync bf16x3 (HMMA). (validated in R4)
// ---------------------------------------------------------------------------
#define XP_BK      32
#define XP_NCHUNK  (INDIM / XP_BK)
#define XP_STRIDE  40
#define XP_MATSZ   (128 * XP_STRIDE * 2)
#define XP_STAGE   (4 * XP_MATSZ)
#define XP_SMEM    (2 * XP_STAGE)

__global__ __launch_bounds__(256) void xproj_mma_kernel(
    const float* __restrict__ bi, const float* __restrict__ bf_,
    const float* __restrict__ bo, const float* __restrict__ bc)
{
    extern __shared__ char smem[];
    const uint32_t sb = smem_u32(smem);
    const int g   = blockIdx.z;
    const int n0  = blockIdx.x * 128;
    const int m0  = blockIdx.y * 128;
    const int tid = threadIdx.x;
    const int wid = tid >> 5;
    const int lane = tid & 31;
    const int warp_m = (wid >> 2) * 64;
    const int warp_n = (wid & 3) * 32;

    const float* bias = (g == 0) ? bi : (g == 1) ? bf_ : (g == 2) ? bo : bc;
    const __nv_bfloat16* Xh = g_Xhi;
    const __nv_bfloat16* Xl = g_Xlo;
    const __nv_bfloat16* Wh = g_Wxhi + (size_t)g * HDIM * INDIM;
    const __nv_bfloat16* Wl = g_Wxlo + (size_t)g * HDIM * INDIM;

    const int lr  = tid >> 2;
    const int lsg = tid & 3;

    float a_cc[4][4][4];
#pragma unroll
    for (int mi = 0; mi < 4; mi++)
#pragma unroll
        for (int ni = 0; ni < 4; ni++)
#pragma unroll
            for (int q = 0; q < 4; q++) a_cc[mi][ni][q] = 0.0f;

    auto load_chunk = [&](int kc, int stg) {
        const int kg = kc * XP_BK;
        const uint32_t base = sb + stg * XP_STAGE;
#pragma unroll
        for (int j = 0; j < 2; j++) {
            const int r = lr + j * 64;
            const uint32_t so = (uint32_t)(r * (XP_STRIDE * 2) + lsg * 16);
            const size_t ga = (size_t)(m0 + r) * INDIM + kg + lsg * 8;
            const size_t gb = (size_t)(n0 + r) * INDIM + kg + lsg * 8;
            CP_ASYNC16(base + so,                 Xh + ga);
            CP_ASYNC16(base + XP_MATSZ + so,      Xl + ga);
            CP_ASYNC16(base + 2 * XP_MATSZ + so,  Wh + gb);
            CP_ASYNC16(base + 3 * XP_MATSZ + so,  Wl + gb);
        }
        CP_COMMIT();
    };

    load_chunk(0, 0);

    const uint32_t a_row = (uint32_t)(warp_m + (lane & 15));
    const uint32_t a_coff = (uint32_t)((lane >> 4) * 8);
    const uint32_t b_row0 = (uint32_t)(warp_n + (lane & 7));
    const uint32_t b_coff = (uint32_t)(((lane >> 3) & 1) * 8);

    for (int kc = 0; kc < XP_NCHUNK; kc++) {
        const int stg = kc & 1;
        if (kc + 1 < XP_NCHUNK) { load_chunk(kc + 1, stg ^ 1); CP_WAIT(1); }
        else                    { CP_WAIT(0); }
        __syncthreads();

        const uint32_t base = sb + stg * XP_STAGE;
#pragma unroll
        for (int ks = 0; ks < 2; ks++) {
            uint32_t ah[4][4], al[4][4], bh[4][2], bl[4][2];
#pragma unroll
            for (int mi = 0; mi < 4; mi++) {
                uint32_t addr = base +
                    (a_row + mi * 16) * (XP_STRIDE * 2) + (ks * 16 + a_coff) * 2;
                LDSM_X4(ah[mi][0], ah[mi][1], ah[mi][2], ah[mi][3], addr);
                LDSM_X4(al[mi][0], al[mi][1], al[mi][2], al[mi][3], addr + XP_MATSZ);
            }
#pragma unroll
            for (int ni = 0; ni < 4; ni++) {
                uint32_t addr = base + 2 * XP_MATSZ +
                    (b_row0 + ni * 8) * (XP_STRIDE * 2) + (ks * 16 + b_coff) * 2;
                LDSM_X2(bh[ni][0], bh[ni][1], addr);
                LDSM_X2(bl[ni][0], bl[ni][1], addr + XP_MATSZ);
            }
#pragma unroll
            for (int mi = 0; mi < 4; mi++)
#pragma unroll
                for (int ni = 0; ni < 4; ni++) {
                    MMA16816(a_cc[mi][ni], ah[mi], bh[ni]);
                    MMA16816(a_cc[mi][ni], ah[mi], bl[ni]);
                    MMA16816(a_cc[mi][ni], al[mi], bh[ni]);
                }
        }
        __syncthreads();
    }

    float* Gg = g_G + (size_t)g * T_STEPS * BATCH * HDIM;
    const int col_base = n0 + warp_n + 2 * (lane & 3);
    const int row_base = m0 + warp_m + (lane >> 2);
    float bv0[4], bv1[4];
#pragma unroll
    for (int ni = 0; ni < 4; ni++) {
        bv0[ni] = __ldg(bias + col_base + ni * 8);
        bv1[ni] = __ldg(bias + col_base + ni * 8 + 1);
    }
#pragma unroll
    for (int mi = 0; mi < 4; mi++) {
        const int r0 = row_base + mi * 16;
#pragma unroll
        for (int ni = 0; ni < 4; ni++) {
            const int c = col_base + ni * 8;
            float2 v0 = make_float2(a_cc[mi][ni][0] + bv0[ni], a_cc[mi][ni][1] + bv1[ni]);
            float2 v1 = make_float2(a_cc[mi][ni][2] + bv0[ni], a_cc[mi][ni][3] + bv1[ni]);
            *(float2*)(Gg + (size_t)r0 * HDIM + c)       = v0;
            *(float2*)(Gg + (size_t)(r0 + 8) * HDIM + c) = v1;
        }
    }
}

// ---------------------------------------------------------------------------
// Kernel 2: persistent tensor-core recurrence.
// 128 CTAs x 256 thr. CTA owns 32 gate-cols (4 gates x 8 h-cols, hbase=cta*8).
// Recurrent weights (hi+lo) resident in smem for all 512 steps.
// Per step: stage h hi/lo in 8 K-chunks (cp.async dbuf), M64xN32xK1024 HMMA x3,
// fused LSTM elementwise, h re-split to bf16 hi/lo globals, sw global barrier.
//
// smem: Whi [32][1032]bf16 (66048 B) | Wlo (66048) | 2 x (h_hi 17408 + h_lo 17408)
// total 201728 B -> 1 CTA/SM. fp32 accum scratch reuses h-staging region.
// ---------------------------------------------------------------------------
#define SC_WSTRIDE 1032
#define SC_WMAT    (32 * SC_WSTRIDE * 2)      // 66048
#define SC_HBASE   (2 * SC_WMAT)              // 132096
#define SC_HSTRIDE 136
#define SC_HMAT    (64 * SC_HSTRIDE * 2)      // 17408
#define SC_HBUF    (2 * SC_HMAT)              // 34816
#define SC_SMEM    (SC_HBASE + 2 * SC_HBUF)   // 201728
#define SC_ACC_OFF SC_HBASE                   // fp32 [64][36] accum scratch

__global__ __launch_bounds__(256, 1) void scan_mma_kernel(
    const float* __restrict__ ret,
    const float* __restrict__ h0,
    const float* __restrict__ c0,
    float* __restrict__ out)
{
    extern __shared__ char smem[];
    const uint32_t sb = smem_u32(smem);
    const int tid  = threadIdx.x;
    const int wid  = tid >> 5;
    const int lane = tid & 31;
    const int hbase = blockIdx.x * 8;
    const int warp_m = (wid >> 1) * 16;   // 0,16,32,48
    const int warp_n = (wid & 1) * 16;    // 0,16

    // ---- load recurrent weights (hi+lo) into smem once ----
#pragma unroll
    for (int pass = 0; pass < 2; pass++) {
        const __nv_bfloat16* src = pass ? g_Whlo : g_Whhi;
        const uint32_t dbase = sb + pass * SC_WMAT;
        for (int i = tid; i < 32 * 128; i += 256) {
            int lr = i >> 7, seg = i & 127;
            int g = lr >> 3, j = lr & 7;
            const __nv_bfloat16* sp =
                src + ((size_t)g * HDIM + hbase + j) * INDIM + seg * 8;
            CP_ASYNC16(dbase + lr * (SC_WSTRIDE * 2) + seg * 16, sp);
        }
    }
    CP_COMMIT();
    CP_WAIT(0);

    // ---- per-thread elementwise pair state ----
    const int p1 = tid + 256;
    const int b_0 = tid >> 3, hl0 = tid & 7;
    const int b_1 = p1 >> 3,  hl1 = p1 & 7;
    const int hc0 = hbase + hl0, hc1 = hbase + hl1;
    const size_t ix0 = (size_t)b_0 * HDIM + hc0;
    const size_t ix1 = (size_t)b_1 * HDIM + hc1;
    float cr0 = c0[ix0], cr1 = c0[ix1];
    float hp0 = h0[ix0], hp1 = h0[ix1];
    const float r0 = ret[hc0], r1 = ret[hc1];

    // init global h hi/lo for t=0 (each CTA covers its own (b,h) pairs)
    {
        __nv_bfloat16 h = __float2bfloat16_rn(hp0);
        g_hhi[ix0] = h;
        g_hlo[ix0] = __float2bfloat16_rn(hp0 - __bfloat162float(h));
        __nv_bfloat16 h2 = __float2bfloat16_rn(hp1);
        g_hhi[ix1] = h2;
        g_hlo[ix1] = __float2bfloat16_rn(hp1 - __bfloat162float(h2));
    }

    unsigned nbar = 0;
#define GBAR() do { nbar++; __threadfence(); __syncthreads(); \
    if (tid == 0) { atomicAdd(&g_bar, 1u); volatile unsigned* _b = &g_bar; \
        while (*_b < nbar * CTAS) { __nanosleep(32); } } \
    __syncthreads(); } while (0)

    GBAR();  // h0 visible everywhere; weights loaded

    auto load_hchunk = [&](int c, int buf) {
        const uint32_t hb = sb + SC_HBASE + buf * SC_HBUF;
#pragma unroll
        for (int j = 0; j < 4; j++) {
            int i = j * 256 + tid;
            int row = i >> 4, seg = i & 15;
            const size_t so = (size_t)row * HDIM + c * 128 + seg * 8;
            uint32_t da = hb + row * (SC_HSTRIDE * 2) + seg * 16;
            CP_ASYNC16(da,           g_hhi + so);
            CP_ASYNC16(da + SC_HMAT, g_hlo + so);
        }
        CP_COMMIT();
    };

    const size_t plane = (size_t)T_STEPS * BATCH * HDIM;
    float* accs = (float*)(smem + SC_ACC_OFF);

    const uint32_t a_row  = (uint32_t)(warp_m + (lane & 15));
    const uint32_t a_coff = (uint32_t)((lane >> 4) * 8);

    for (int t = 0; t < T_STEPS; t++) {
        const float* Gt = g_G + (size_t)t * BATCH * HDIM;
        // prefetch gate preactivations (DRAM, latency hidden by chunk work)
        float G00 = Gt[0 * plane + ix0], G01 = Gt[1 * plane + ix0];
        float G02 = Gt[2 * plane + ix0], G03 = Gt[3 * plane + ix0];
        float G10 = Gt[0 * plane + ix1], G11 = Gt[1 * plane + ix1];
        float G12 = Gt[2 * plane + ix1], G13 = Gt[3 * plane + ix1];

        float dacc[2][2][4];   // [k-parity][n-tile][4]
#pragma unroll
        for (int kp = 0; kp < 2; kp++)
#pragma unroll
            for (int ni = 0; ni < 2; ni++)
#pragma unroll
                for (int q = 0; q < 4; q++) dacc[kp][ni][q] = 0.0f;

        load_hchunk(0, 0);
        for (int c = 0; c < 8; c++) {
            const int buf = c & 1;
            if (c < 7) { load_hchunk(c + 1, buf ^ 1); CP_WAIT(1); }
            else       { CP_WAIT(0); }
            __syncthreads();

            const uint32_t hb = sb + SC_HBASE + buf * SC_HBUF;
#pragma unroll
            for (int ks = 0; ks < 8; ks++) {
                uint32_t ah[4], al[4];
                uint32_t addrA = hb + a_row * (SC_HSTRIDE * 2)
                                    + (ks * 16 + a_coff) * 2;
                LDSM_X4(ah[0], ah[1], ah[2], ah[3], addrA);
                LDSM_X4(al[0], al[1], al[2], al[3], addrA + SC_HMAT);
#pragma unroll
                for (int ni = 0; ni < 2; ni++) {
                    uint32_t bh[2], bl[2];
                    uint32_t addrB = sb +
                        (warp_n + ni * 8 + (lane & 7)) * (SC_WSTRIDE * 2) +
                        ((c * 128 + ks * 16) + ((lane >> 3) & 1) * 8) * 2;
                    LDSM_X2(bh[0], bh[1], addrB);
                    LDSM_X2(bl[0], bl[1], addrB + SC_WMAT);
                    MMA16816(dacc[ks & 1][ni], ah, bh);
                    MMA16816(dacc[ks & 1][ni], ah, bl);
                    MMA16816(dacc[ks & 1][ni], al, bh);
                }
            }
            __syncthreads();
        }

        // store warp fragments to smem accum [64][36]
        {
            const int arow = warp_m + (lane >> 2);
            const int acol = warp_n + 2 * (lane & 3);
#pragma unroll
            for (int ni = 0; ni < 2; ni++) {
                float2 v0 = make_float2(dacc[0][ni][0] + dacc[1][ni][0],
                                        dacc[0][ni][1] + dacc[1][ni][1]);
                float2 v1 = make_float2(dacc[0][ni][2] + dacc[1][ni][2],
                                        dacc[0][ni][3] + dacc[1][ni][3]);
                *(float2*)&accs[arow * 36 + acol + ni * 8]       = v0;
                *(float2*)&accs[(arow + 8) * 36 + acol + ni * 8] = v1;
            }
        }
        __syncthreads();

        // fused LSTM elementwise for the thread's two (b,h) pairs
        float* outT = out + (size_t)t * BATCH * HDIM;
        {
            float gi = accs[b_0 * 36 + 0  + hl0] + G00;
            float gf = accs[b_0 * 36 + 8  + hl0] + G01;
            float go = accs[b_0 * 36 + 16 + hl0] + G02;
            float gc = accs[b_0 * 36 + 24 + hl0] + G03;
            float i_t = 1.0f / (1.0f + __expf(-gi));
            float f_t = 1.0f / (1.0f + __expf(-gf));
            float o_t = 1.0f / (1.0f + __expf(-go));
            float g_t = tanhf(gc);
            cr0 = cr0 * f_t + i_t * g_t;
            float hl_ = o_t * tanhf(cr0);
            hp0 = r0 * hp0 + (1.0f - r0) * hl_;
            outT[ix0] = hp0;
            __nv_bfloat16 hh = __float2bfloat16_rn(hp0);
            g_hhi[ix0] = hh;
            g_hlo[ix0] = __float2bfloat16_rn(hp0 - __bfloat162float(hh));
        }
        {
            float gi = accs[b_1 * 36 + 0  + hl1] + G10;
            float gf = accs[b_1 * 36 + 8  + hl1] + G11;
            float go = accs[b_1 * 36 + 16 + hl1] + G12;
            float gc = accs[b_1 * 36 + 24 + hl1] + G13;
            float i_t = 1.0f / (1.0f + __expf(-gi));
            float f_t = 1.0f / (1.0f + __expf(-gf));
            float o_t = 1.0f / (1.0f + __expf(-go));
            float g_t = tanhf(gc);
            cr1 = cr1 * f_t + i_t * g_t;
            float hl_ = o_t * tanhf(cr1);
            hp1 = r1 * hp1 + (1.0f - r1) * hl_;
            outT[ix1] = hp1;
            __nv_bfloat16 hh = __float2bfloat16_rn(hp1);
            g_hhi[ix1] = hh;
            g_hlo[ix1] = __float2bfloat16_rn(hp1 - __bfloat162float(hh));
        }

        GBAR();
    }

    // tail: h_T (= outs[T-1] values held in regs) and c_T
    {
        float* hT = out + (size_t)T_STEPS * BATCH * HDIM;
        float* cT = hT + (size_t)BATCH * HDIM;
        hT[ix0] = hp0; hT[ix1] = hp1;
        cT[ix0] = cr0; cT[ix1] = cr1;
    }
#undef GBAR
}

// ---------------------------------------------------------------------------
extern "C" void kernel_launch(void* const* d_in, const int* in_sizes, int n_in,
                              void* d_out, int out_size)
{
    const float* X    = (const float*)d_in[0];
    const float* h0   = (const float*)d_in[1];
    const float* c0   = (const float*)d_in[2];
    const float* w_xi = (const float*)d_in[3];
    const float* w_xf = (const float*)d_in[4];
    const float* w_xo = (const float*)d_in[5];
    const float* w_xc = (const float*)d_in[6];
    const float* w_hi = (const float*)d_in[7];
    const float* w_hf = (const float*)d_in[8];
    const float* w_ho = (const float*)d_in[9];
    const float* w_hc = (const float*)d_in[10];
    const float* b_i  = (const float*)d_in[11];
    const float* b_f  = (const float*)d_in[12];
    const float* b_o  = (const float*)d_in[13];
    const float* b_c  = (const float*)d_in[14];
    const float* rr   = (const float*)d_in[15];

    float* out = (float*)d_out;

    void* bar_ptr = nullptr;
    cudaGetSymbolAddress(&bar_ptr, g_bar);
    cudaMemsetAsync(bar_ptr, 0, sizeof(unsigned));

    void *wxhi, *wxlo, *whhi, *whlo;
    cudaGetSymbolAddress(&wxhi, g_Wxhi);
    cudaGetSymbolAddress(&wxlo, g_Wxlo);
    cudaGetSymbolAddress(&whhi, g_Whhi);
    cudaGetSymbolAddress(&whlo, g_Whlo);

    static int attr_set = 0;
    if (!attr_set) {
        cudaFuncSetAttribute(xproj_mma_kernel,
                             cudaFuncAttributeMaxDynamicSharedMemorySize, XP_SMEM);
        cudaFuncSetAttribute(scan_mma_kernel,
                             cudaFuncAttributeMaxDynamicSharedMemorySize, SC_SMEM);
        attr_set = 1;
    }

    // Preps: bf16 hi/lo splits (input + both weight sets)
    xsplit_kernel<<<(T_STEPS * BATCH * INDIM) / (4 * 256), 256>>>(X);
    wprep_kernel<<<dim3(32, 32, 4), dim3(32, 8)>>>(
        w_xi, w_xf, w_xo, w_xc, (__nv_bfloat16*)wxhi, (__nv_bfloat16*)wxlo);
    wprep_kernel<<<dim3(32, 32, 4), dim3(32, 8)>>>(
        w_hi, w_hf, w_ho, w_hc, (__nv_bfloat16*)whhi, (__nv_bfloat16*)whlo);

    // Phase 1: gate preactivations via HMMA bf16x3
    {
        dim3 grid(HDIM / 128, (T_STEPS * BATCH) / 128, 4);
        xproj_mma_kernel<<<grid, 256, XP_SMEM>>>(b_i, b_f, b_o, b_c);
    }

    // Phase 2: persistent tensor-core scan
    scan_mma_kernel<<<CTAS, 256, SC_SMEM>>>(rr, h0, c0, out);
}